// round 13
// baseline (speedup 1.0000x reference)
#include <cuda_runtime.h>
#include <cuda_fp16.h>
#include <cstdint>

#define B_SZ 8
#define NPTS 16384
#define MSRC 1024
#define C1   128
#define C2   256
#define CIN  384
#define CO   256
#define BN_EPS 1e-5f

// ---------------------------------------------------------------------------
// Scratch (allocation-free)
// ---------------------------------------------------------------------------
__device__ __align__(256) float  g_Zt [(size_t)B_SZ * MSRC * CO];
__device__ __align__(256) int4   g_nni[(size_t)B_SZ * NPTS];
__device__ __align__(256) float4 g_nnw[(size_t)B_SZ * NPTS];
__device__ __align__(256) __half g_W0 [CO * C1];
__device__ __align__(256) __half g_W1 [CO * CO];
__device__ __align__(256) __half g_T  [(size_t)B_SZ * NPTS * C1];   // tfeat^T fp16
__device__ __align__(256) __half g_Y0 [(size_t)B_SZ * NPTS * CO];   // Y0^T fp16

// ---------------------------------------------------------------------------
// PTX helpers (sm_100-safe)
// ---------------------------------------------------------------------------
__device__ __forceinline__ uint32_t smem_u32(const void* p) {
    uint32_t a;
    asm("{ .reg .u64 t; cvta.to.shared.u64 t, %1; cvt.u32.u64 %0, t; }" : "=r"(a) : "l"(p));
    return a;
}
#define CP16(dst, src) \
    asm volatile("cp.async.cg.shared.global [%0], [%1], 16;" :: "r"(dst), "l"(src))
#define CP_COMMIT() asm volatile("cp.async.commit_group;" ::: "memory")
#define CP_WAIT(n)  asm volatile("cp.async.wait_group %0;" :: "n"(n) : "memory")

#define LDSM4(r, addr) \
    asm volatile("ldmatrix.sync.aligned.m8n8.x4.shared.b16 {%0,%1,%2,%3}, [%4];" \
        : "=r"((r)[0]), "=r"((r)[1]), "=r"((r)[2]), "=r"((r)[3]) : "r"(addr))

#define MMA_F16(d, a, b0, b1) \
    asm volatile("mma.sync.aligned.m16n8k16.row.col.f32.f16.f16.f32 " \
        "{%0,%1,%2,%3}, {%4,%5,%6,%7}, {%8,%9}, {%0,%1,%2,%3};" \
        : "+f"((d)[0]), "+f"((d)[1]), "+f"((d)[2]), "+f"((d)[3]) \
        : "r"((a)[0]), "r"((a)[1]), "r"((a)[2]), "r"((a)[3]), "r"(b0), "r"(b1))

// ===========================================================================
// Fused small-kernel dispatcher bodies
// ===========================================================================

// ---- three_nn: 2 target points per thread. One block = 512 points. --------
__device__ __forceinline__ void nn_body(char* dsm,
    const float* __restrict__ target, const float* __restrict__ source,
    int4* __restrict__ nni, float4* __restrict__ nnw, int bx, int b)
{
    float4* s = (float4*)dsm;       // 16 KB
    const int t = threadIdx.x;
    const int ia = bx * 512 + t;
    const int ib = ia + 256;
    const float* src = source + (size_t)b * MSRC * 3;
    for (int j = t; j < MSRC; j += 256) {
        const float x = src[j * 3 + 0], y = src[j * 3 + 1], z = src[j * 3 + 2];
        s[j] = make_float4(x, y, z, x * x + y * y + z * z);
    }
    __syncthreads();

    const float* tpa = target + ((size_t)b * NPTS + ia) * 3;
    const float* tpb = target + ((size_t)b * NPTS + ib) * 3;
    const float pax = tpa[0], pay = tpa[1], paz = tpa[2];
    const float pbx = tpb[0], pby = tpb[1], pbz = tpb[2];
    const float qax = -2.0f * pax, qay = -2.0f * pay, qaz = -2.0f * paz;
    const float qbx = -2.0f * pbx, qby = -2.0f * pby, qbz = -2.0f * pbz;

    float a0 = 3.4e38f, a1 = 3.4e38f, a2 = 3.4e38f;
    float f0 = 3.4e38f, f1 = 3.4e38f, f2 = 3.4e38f;
    int   ja0 = 0, ja1 = 0, ja2 = 0, jb0 = 0, jb1 = 0, jb2 = 0;
    #pragma unroll 4
    for (int j = 0; j < MSRC; j++) {
        const float4 v = s[j];
        const float ea = fmaf(qax, v.x, fmaf(qay, v.y, fmaf(qaz, v.z, v.w)));
        const float eb = fmaf(qbx, v.x, fmaf(qby, v.y, fmaf(qbz, v.z, v.w)));
        if (ea < a0)      { a2 = a1; ja2 = ja1; a1 = a0; ja1 = ja0; a0 = ea; ja0 = j; }
        else if (ea < a1) { a2 = a1; ja2 = ja1; a1 = ea; ja1 = j; }
        else if (ea < a2) { a2 = ea; ja2 = j; }
        if (eb < f0)      { f2 = f1; jb2 = jb1; f1 = f0; jb1 = jb0; f0 = eb; jb0 = j; }
        else if (eb < f1) { f2 = f1; jb2 = jb1; f1 = eb; jb1 = j; }
        else if (eb < f2) { f2 = eb; jb2 = j; }
    }
    {
        float d[3]; const int jj[3] = {ja0, ja1, ja2};
        #pragma unroll
        for (int k = 0; k < 3; k++) {
            const float4 v = s[jj[k]];
            const float dx = pax - v.x, dy = pay - v.y, dz = paz - v.z;
            d[k] = dx * dx + dy * dy + dz * dz;
        }
        const float r0 = 1.0f / (d[0] + 1e-8f), r1 = 1.0f / (d[1] + 1e-8f), r2 = 1.0f / (d[2] + 1e-8f);
        const float rs = 1.0f / (r0 + r1 + r2);
        nni[(size_t)b * NPTS + ia] = make_int4(ja0, ja1, ja2, 0);
        nnw[(size_t)b * NPTS + ia] = make_float4(r0 * rs, r1 * rs, r2 * rs, 0.0f);
    }
    {
        float d[3]; const int jj[3] = {jb0, jb1, jb2};
        #pragma unroll
        for (int k = 0; k < 3; k++) {
            const float4 v = s[jj[k]];
            const float dx = pbx - v.x, dy = pby - v.y, dz = pbz - v.z;
            d[k] = dx * dx + dy * dy + dz * dz;
        }
        const float r0 = 1.0f / (d[0] + 1e-8f), r1 = 1.0f / (d[1] + 1e-8f), r2 = 1.0f / (d[2] + 1e-8f);
        const float rs = 1.0f / (r0 + r1 + r2);
        nni[(size_t)b * NPTS + ib] = make_int4(jb0, jb1, jb2, 0);
        nnw[(size_t)b * NPTS + ib] = make_float4(r0 * rs, r1 * rs, r2 * rs, 0.0f);
    }
}

// ---- Zt = (w0[:, :256] @ sfeat)^T, fp32 (keeps interp path exact) ---------
__device__ __forceinline__ void zt_body(char* dsm,
    const float* __restrict__ w0, const float* __restrict__ sfeat,
    float* __restrict__ Zt, int J0b, int O0b, int b)
{
    constexpr int BK = 16, TM = 8, TN = 8;
    float (*Ss)[128] = (float(*)[128])dsm;            // 8 KB
    float (*Ws)[128] = (float(*)[128])(dsm + 8192);   // 8 KB
    const int J0 = J0b * 128, O0 = O0b * 128;
    const float* sf = sfeat + (size_t)b * C2 * MSRC;
    const int tid = threadIdx.x;
    const int rowO = tid >> 2, colK = (tid & 3) * 4;
    const int rowK = tid >> 5, colJ = (tid & 31) * 4;
    const int tj = (tid >> 4) * TM, to = (tid & 15) * TN;
    float acc[TM][TN];
    #pragma unroll
    for (int i = 0; i < TM; i++)
        #pragma unroll
        for (int j = 0; j < TN; j++) acc[i][j] = 0.0f;
    for (int k0 = 0; k0 < C2; k0 += BK) {
        #pragma unroll
        for (int p = 0; p < 2; p++) {
            const int r = rowO + p * 64;
            const float4 v = *(const float4*)(w0 + (size_t)(O0 + r) * CIN + k0 + colK);
            Ws[colK + 0][r] = v.x; Ws[colK + 1][r] = v.y;
            Ws[colK + 2][r] = v.z; Ws[colK + 3][r] = v.w;
        }
        #pragma unroll
        for (int p = 0; p < 2; p++) {
            const int r = rowK + p * 8;
            *(float4*)&Ss[r][colJ] = *(const float4*)(sf + (size_t)(k0 + r) * MSRC + J0 + colJ);
        }
        __syncthreads();
        #pragma unroll
        for (int kk = 0; kk < BK; kk++) {
            float a[TM], w[TN];
            #pragma unroll
            for (int i = 0; i < TM; i += 4) *(float4*)&a[i] = *(const float4*)&Ss[kk][tj + i];
            #pragma unroll
            for (int j = 0; j < TN; j += 4) *(float4*)&w[j] = *(const float4*)&Ws[kk][to + j];
            #pragma unroll
            for (int i = 0; i < TM; i++)
                #pragma unroll
                for (int j = 0; j < TN; j++) acc[i][j] = fmaf(a[i], w[j], acc[i][j]);
        }
        __syncthreads();
    }
    float* Zb = Zt + (size_t)b * MSRC * CO;
    #pragma unroll
    for (int i = 0; i < TM; i++)
        #pragma unroll
        for (int j = 0; j < TN; j += 4) {
            float4 v = make_float4(acc[i][j], acc[i][j+1], acc[i][j+2], acc[i][j+3]);
            *(float4*)(Zb + (size_t)(J0 + tj + i) * CO + O0 + to + j) = v;
        }
}

// ---- tfeat transpose: (B,C1,N) fp32 -> (B,N,C1) fp16 ----------------------
__device__ __forceinline__ void tfeat_body(char* dsm,
    const float* __restrict__ tfeat, __half* __restrict__ T,
    int nb, int cb, int b)
{
    float (*sm)[33] = (float(*)[33])dsm;   // 4224 B
    const int n0 = nb * 32, c0 = cb * 32;
    const int tx = threadIdx.x & 31, ty = threadIdx.x >> 5;
    const float* src = tfeat + (size_t)b * C1 * NPTS;
    #pragma unroll
    for (int i = 0; i < 4; i++) {
        const int c = ty + i * 8;
        sm[c][tx] = src[(size_t)(c0 + c) * NPTS + n0 + tx];
    }
    __syncthreads();
    #pragma unroll
    for (int i = 0; i < 4; i++) {
        const int n = ty + i * 8;
        T[((size_t)b * NPTS + n0 + n) * C1 + c0 + tx] = __float2half_rn(sm[tx][n]);
    }
}

// ---- dispatcher -----------------------------------------------------------
// blocks [0,256): nn   [256,384): zt   [384, 384+16384): tfeat_t
__global__ void __launch_bounds__(256)
small_fused_kernel(const float* __restrict__ target, const float* __restrict__ source,
                   const float* __restrict__ w0, const float* __restrict__ sfeat,
                   const float* __restrict__ tfeat,
                   int4* __restrict__ nni, float4* __restrict__ nnw,
                   float* __restrict__ Zt, __half* __restrict__ T)
{
    extern __shared__ __align__(16) char dsm[];
    const int id = blockIdx.x;
    if (id < 256) {
        nn_body(dsm, target, source, nni, nnw, id & 31, id >> 5);
    } else if (id < 384) {
        const int z = id - 256;            // (8, 2, 8) -> 128 blocks
        zt_body(dsm, w0, sfeat, Zt, z & 7, (z >> 3) & 1, z >> 4);
    } else {
        const int t = id - 384;            // (512, 4, 8) -> 16384 blocks
        tfeat_body(dsm, tfeat, T, t & 511, (t >> 9) & 3, t >> 11);
    }
}

// ---------------------------------------------------------------------------
// Merged weight convert (W0 slice + W1, single fp16 planes)
// ---------------------------------------------------------------------------
__global__ void __launch_bounds__(256)
conv_w2_kernel(const float* __restrict__ w0, const float* __restrict__ w1,
               __half* __restrict__ W0, __half* __restrict__ W1)
{
    const int idx = blockIdx.x * 256 + threadIdx.x;
    if (idx < CO * C1) {
        const int o = idx / C1, k = idx % C1;
        W0[idx] = __float2half_rn(w0[(size_t)o * CIN + C2 + k]);
    } else {
        const int j = idx - CO * C1;
        if (j < CO * CO) {
            const int o = j / CO, k = j % CO;
            W1[j] = __float2half_rn(w1[(size_t)o * CO + k]);
        }
    }
}

// ---------------------------------------------------------------------------
// GEMM kernels: round-8 architecture (proven 356 us). fp16 single-pass,
// CTA 128m x 128n, BK=64, 8 warps (4m x 2n), cp.async double buffer, 2 CTA/SM.
// ---------------------------------------------------------------------------
template<int KW, bool L0GATHER>
__global__ void __launch_bounds__(256, 2)
mma_layer_kernel(const __half* __restrict__ W, const __half* __restrict__ X,
                 float* __restrict__ outF, __half* __restrict__ outH,
                 const float* __restrict__ gam, const float* __restrict__ bet,
                 const float* __restrict__ mu,  const float* __restrict__ var,
                 const int4* __restrict__ nni, const float4* __restrict__ nnw,
                 const float* __restrict__ Zt)
{
    constexpr int KC  = KW / 64;
    constexpr int TS  = 128 * 144;
    constexpr int BUF = 2 * TS;
    extern __shared__ __align__(16) char smem[];
    const uint32_t sb = smem_u32(smem);

    const int tid = threadIdx.x, lane = tid & 31, wid = tid >> 5;
    const int wm = wid >> 1, wn = wid & 1;
    const int b = blockIdx.z, n0 = blockIdx.x * 128, m0 = blockIdx.y * 128;

    const __half* A_g = W + (size_t)m0 * KW;
    const __half* B_g = X + ((size_t)b * NPTS + n0) * KW;

    const int lr = tid >> 3;
    const int lc = (tid & 7) * 8;

    float acc[2][8][4];
    #pragma unroll
    for (int i = 0; i < 2; i++)
        #pragma unroll
        for (int j = 0; j < 8; j++)
            #pragma unroll
            for (int q = 0; q < 4; q++) acc[i][j][q] = 0.0f;

    #pragma unroll
    for (int it = 0; it < 4; it++) {
        const int r = lr + it * 32;
        const uint32_t so = (uint32_t)(r * 144 + lc * 2);
        CP16(sb + so,      A_g + (size_t)r * KW + lc);
        CP16(sb + TS + so, B_g + (size_t)r * KW + lc);
    }
    CP_COMMIT();

    for (int c = 0; c < KC; c++) {
        if (c + 1 < KC) {
            const int k0 = (c + 1) * 64;
            const uint32_t bufo = (uint32_t)(((c + 1) & 1) * BUF);
            #pragma unroll
            for (int it = 0; it < 4; it++) {
                const int r = lr + it * 32;
                const uint32_t so = bufo + (uint32_t)(r * 144 + lc * 2);
                CP16(sb + so,      A_g + (size_t)r * KW + k0 + lc);
                CP16(sb + TS + so, B_g + (size_t)r * KW + k0 + lc);
            }
            CP_COMMIT();
            CP_WAIT(1);
        } else {
            CP_WAIT(0);
        }
        __syncthreads();

        const uint32_t base = sb + (uint32_t)((c & 1) * BUF);
        #pragma unroll
        for (int kk = 0; kk < 4; kk++) {
            uint32_t ah[2][4];
            #pragma unroll
            for (int mt = 0; mt < 2; mt++) {
                const uint32_t ad = base
                    + (uint32_t)((wm * 32 + mt * 16 + (lane & 15)) * 144
                                 + (kk * 16 + ((lane >> 4) << 3)) * 2);
                LDSM4(ah[mt], ad);
            }
            #pragma unroll
            for (int ng = 0; ng < 4; ng++) {
                uint32_t bh[4];
                const uint32_t bd = base + TS
                    + (uint32_t)((wn * 64 + ng * 16 + (lane & 7) + ((lane >> 4) << 3)) * 144
                                 + (kk * 16 + (((lane >> 3) & 1) << 3)) * 2);
                LDSM4(bh, bd);
                #pragma unroll
                for (int mt = 0; mt < 2; mt++)
                    #pragma unroll
                    for (int hh = 0; hh < 2; hh++)
                        MMA_F16(acc[mt][ng * 2 + hh], ah[mt], bh[2 * hh], bh[2 * hh + 1]);
            }
        }
        __syncthreads();
    }

    if (!L0GATHER) {
        #pragma unroll
        for (int mt = 0; mt < 2; mt++) {
            const int o0 = m0 + wm * 32 + mt * 16 + (lane >> 2);
            const float s0 = gam[o0] * rsqrtf(var[o0] + BN_EPS);
            const float c0 = bet[o0] - mu[o0] * s0;
            const int o1 = o0 + 8;
            const float s1 = gam[o1] * rsqrtf(var[o1] + BN_EPS);
            const float c1 = bet[o1] - mu[o1] * s1;
            #pragma unroll
            for (int j = 0; j < 8; j++) {
                const int n = n0 + wn * 64 + j * 8 + (lane & 3) * 2;
                float2 v0, v1;
                v0.x = fmaxf(fmaf(acc[mt][j][0], s0, c0), 0.0f);
                v0.y = fmaxf(fmaf(acc[mt][j][1], s0, c0), 0.0f);
                v1.x = fmaxf(fmaf(acc[mt][j][2], s1, c1), 0.0f);
                v1.y = fmaxf(fmaf(acc[mt][j][3], s1, c1), 0.0f);
                *(float2*)(outF + ((size_t)b * CO + o0) * NPTS + n) = v0;
                *(float2*)(outF + ((size_t)b * CO + o1) * NPTS + n) = v1;
            }
        }
    } else {
        float* S = (float*)smem;   // 128 x 132 fp32 = 67584 <= 73728
        #pragma unroll
        for (int mt = 0; mt < 2; mt++) {
            const int ol = wm * 32 + mt * 16 + (lane >> 2);
            #pragma unroll
            for (int j = 0; j < 8; j++) {
                const int nl = wn * 64 + j * 8 + (lane & 3) * 2;
                S[(nl + 0) * 132 + ol]     = acc[mt][j][0];
                S[(nl + 1) * 132 + ol]     = acc[mt][j][1];
                S[(nl + 0) * 132 + ol + 8] = acc[mt][j][2];
                S[(nl + 1) * 132 + ol + 8] = acc[mt][j][3];
            }
        }
        __syncthreads();

        const size_t bn = (size_t)b * NPTS;
        const float* Zb = Zt + (size_t)b * MSRC * CO;
        #pragma unroll 2
        for (int it = 0; it < 16; it++) {
            const int item = tid + it * 256;
            const int nl = item >> 5, o4 = (item & 31) * 4;
            const int n = n0 + nl, o = m0 + o4;
            float4 v = *(float4*)(S + nl * 132 + o4);
            const int4   ji = nni[bn + n];
            const float4 jw = nnw[bn + n];
            const float4 z0 = *(const float4*)(Zb + (size_t)ji.x * CO + o);
            const float4 z1 = *(const float4*)(Zb + (size_t)ji.y * CO + o);
            const float4 z2 = *(const float4*)(Zb + (size_t)ji.z * CO + o);
            v.x += jw.x * z0.x + jw.y * z1.x + jw.z * z2.x;
            v.y += jw.x * z0.y + jw.y * z1.y + jw.z * z2.y;
            v.z += jw.x * z0.z + jw.y * z1.z + jw.z * z2.z;
            v.w += jw.x * z0.w + jw.y * z1.w + jw.z * z2.w;
            const float4 g4 = *(const float4*)(gam + o);
            const float4 b4 = *(const float4*)(bet + o);
            const float4 m4 = *(const float4*)(mu  + o);
            const float4 q4 = *(const float4*)(var + o);
            const float sx = g4.x * rsqrtf(q4.x + BN_EPS);
            const float sy = g4.y * rsqrtf(q4.y + BN_EPS);
            const float sz = g4.z * rsqrtf(q4.z + BN_EPS);
            const float sw = g4.w * rsqrtf(q4.w + BN_EPS);
            union { __half h[4]; uint2 u; } H;
            H.h[0] = __float2half_rn(fmaxf(fmaf(v.x, sx, b4.x - m4.x * sx), 0.0f));
            H.h[1] = __float2half_rn(fmaxf(fmaf(v.y, sy, b4.y - m4.y * sy), 0.0f));
            H.h[2] = __float2half_rn(fmaxf(fmaf(v.z, sz, b4.z - m4.z * sz), 0.0f));
            H.h[3] = __float2half_rn(fmaxf(fmaf(v.w, sw, b4.w - m4.w * sw), 0.0f));
            *(uint2*)(outH + (bn + n) * CO + o) = H.u;
        }
    }
}

// ---------------------------------------------------------------------------
extern "C" void kernel_launch(void* const* d_in, const int* in_sizes, int n_in,
                              void* d_out, int out_size)
{
    const float* target = (const float*)d_in[0];
    const float* source = (const float*)d_in[1];
    const float* tfeat  = (const float*)d_in[2];
    const float* sfeat  = (const float*)d_in[3];
    const float* w0     = (const float*)d_in[4];
    const float* g0     = (const float*)d_in[5];
    const float* b0     = (const float*)d_in[6];
    const float* mu0    = (const float*)d_in[7];
    const float* var0   = (const float*)d_in[8];
    const float* w1     = (const float*)d_in[9];
    const float* g1     = (const float*)d_in[10];
    const float* b1     = (const float*)d_in[11];
    const float* mu1    = (const float*)d_in[12];
    const float* var1   = (const float*)d_in[13];
    float* out = (float*)d_out;

    float*  Zt;  cudaGetSymbolAddress((void**)&Zt,  g_Zt);
    int4*   nni; cudaGetSymbolAddress((void**)&nni, g_nni);
    float4* nnw; cudaGetSymbolAddress((void**)&nnw, g_nnw);
    __half *W0, *W1, *T, *Y0;
    cudaGetSymbolAddress((void**)&W0, g_W0); cudaGetSymbolAddress((void**)&W1, g_W1);
    cudaGetSymbolAddress((void**)&T,  g_T);  cudaGetSymbolAddress((void**)&Y0, g_Y0);

    constexpr int SMEM_SMALL = 16384;
    constexpr int SMEM_MMA   = 2 * 2 * 128 * 144;  // 73728
    cudaFuncSetAttribute(small_fused_kernel,
                         cudaFuncAttributeMaxDynamicSharedMemorySize, SMEM_SMALL);
    cudaFuncSetAttribute(mma_layer_kernel<C1, true>,
                         cudaFuncAttributeMaxDynamicSharedMemorySize, SMEM_MMA);
    cudaFuncSetAttribute(mma_layer_kernel<CO, false>,
                         cudaFuncAttributeMaxDynamicSharedMemorySize, SMEM_MMA);

    // 1) fused: three_nn (256 blk) + Zt (128 blk) + tfeat^T (16384 blk)
    {
        const int nblocks = 256 + 128 + 16384;
        small_fused_kernel<<<nblocks, 256, SMEM_SMALL>>>(
            target, source, w0, sfeat, tfeat, nni, nnw, Zt, T);
    }
    // 2) weight converts (merged)
    conv_w2_kernel<<<(CO * C1 + CO * CO + 255) / 256, 256>>>(w0, w1, W0, W1);
    // 3) layer 0: W0 @ T^T + gather(Zt) + BN + ReLU -> Y0^T fp16
    {
        dim3 grid(NPTS / 128, CO / 128, B_SZ);
        mma_layer_kernel<C1, true><<<grid, 256, SMEM_MMA>>>(
            W0, T, nullptr, Y0, g0, b0, mu0, var0, nni, nnw, Zt);
    }
    // 4) layer 1: W1 @ Y0^T + BN + ReLU -> out fp32 (B, CO, N)
    {
        dim3 grid(NPTS / 128, CO / 128, B_SZ);
        mma_layer_kernel<CO, false><<<grid, 256, SMEM_MMA>>>(
            W1, Y0, out, nullptr, g1, b1, mu1, var1, nullptr, nullptr, nullptr);
    }
    (void)in_sizes; (void)n_in; (void)out_size;
}